// round 16
// baseline (speedup 1.0000x reference)
#include <cuda_runtime.h>

#define B_  8
#define C_  256
#define C8  32
#define H_  96
#define W_  96
#define HW  9216
#define PP  280

typedef unsigned long long ull;

// ---------------- scratch (device globals; no allocation allowed) ----------------
__device__ float g_P1[B_*C_*PP];       // PSP(x_1)  [8,256,280]
__device__ float g_P2[B_*C_*PP];       // PSP(x)    [8,256,280]
__device__ float g_pk[B_*C8*PP];       // projk     [8,32,280]
__device__ float g_Sp[B_*20*C8];       // per-tile partial sums of projk
__device__ float g_G [B_*C_*C8];       // P1 . projk^T  [8,256,32]
__device__ float g_aff[B_*C_*C8];      // sigmoid(...)  [8,256,32]
__device__ float g_ya[B_*C8*HW];       // conv partial (c 0..127)
__device__ float g_yb[B_*C8*HW];       // conv partial (c 128..255)
// duplicated + padded conv weights: [c][j][rr][4] float2 (k=3 pad = 0)
__device__ __align__(16) float2 g_w2p[C_*C8*12];

// ---------------- f32x2 helpers ----------------
__device__ __forceinline__ ull pk2f(float lo, float hi) {
    ull r;
    asm("mov.b64 %0, {%1, %2};" : "=l"(r) : "f"(lo), "f"(hi));
    return r;
}
__device__ __forceinline__ void upk2f(ull v, float& lo, float& hi) {
    asm("mov.b64 {%0, %1}, %2;" : "=f"(lo), "=f"(hi) : "l"(v));
}
__device__ __forceinline__ void fma2(ull& acc, ull a, ull b) {
    asm("fma.rn.f32x2 %0, %1, %2, %0;" : "+l"(acc) : "l"(a), "l"(b));
}
__device__ __forceinline__ ull add2(ull a, ull b) {
    ull r;
    asm("add.rn.f32x2 %0, %1, %2;" : "=l"(r) : "l"(a), "l"(b));
    return r;
}

// ---------------- cp.async helpers ----------------
__device__ __forceinline__ unsigned s2u(const void* p) {
    return (unsigned)__cvta_generic_to_shared(p);
}
__device__ __forceinline__ void cpa4z(unsigned d, const void* s, int sz) {
    asm volatile("cp.async.ca.shared.global [%0], [%1], 4, %2;" :: "r"(d), "l"(s), "r"(sz));
}
__device__ __forceinline__ void cpa16(unsigned d, const void* s) {
    asm volatile("cp.async.cg.shared.global [%0], [%1], 16;" :: "r"(d), "l"(s));
}
__device__ __forceinline__ void cpa16z(unsigned d, const void* s, int sz) {
    asm volatile("cp.async.cg.shared.global [%0], [%1], 16, %2;" :: "r"(d), "l"(s), "r"(sz));
}
#define CP_COMMIT() asm volatile("cp.async.commit_group;" ::: "memory")
#define CP_WAIT1()  asm volatile("cp.async.wait_group 1;"  ::: "memory")
#define CP_WAIT0()  asm volatile("cp.async.wait_group 0;"  ::: "memory")

// ---------------- K0: duplicate conv weights, padded [c][j][rr][4] ----------------
__global__ void __launch_bounds__(256) w2prep_kernel(const float* __restrict__ con) {
    int idx = blockIdx.x * 256 + threadIdx.x;      // < 98304
    int c = idx / 384, rem = idx - c * 384;
    int j = rem / 12, r2 = rem - j * 12;
    int rr = r2 >> 2, k = r2 & 3;
    float w = (k < 3) ? con[j * 2304 + c * 9 + rr * 3 + k] : 0.f;
    g_w2p[idx] = make_float2(w, w);
}

// ---------------- K1: adaptive pyramid pooling — column prefix-sum version ----------
__global__ void __launch_bounds__(256) pool_kernel(const float* __restrict__ src,
                                                   int which) {
    __shared__ float tile[96][97];
    __shared__ float rb[30][96];
    int ch = blockIdx.x;                           // b*C + c
    float* dst = which ? g_P2 : g_P1;

    const float4* s4 = (const float4*)(src + (size_t)ch * HW);
    for (int i = threadIdx.x; i < HW / 4; i += 256) {
        float4 v = s4[i];
        int li = i * 4, r = li / 96, c0 = li - r * 96;
        tile[r][c0] = v.x; tile[r][c0+1] = v.y; tile[r][c0+2] = v.z; tile[r][c0+3] = v.w;
    }
    __syncthreads();

    // Phase B: in-place inclusive column prefix (threads 0..95, conflict-free)
    if (threadIdx.x < 96) {
        int w = threadIdx.x;
        float acc = 0.f;
        #pragma unroll 8
        for (int h = 0; h < 96; h++) { acc += tile[h][w]; tile[h][w] = acc; }
    }
    __syncthreads();

    // 30 1D row-bins from prefix differences; literal divisors only (no IDIV).
    for (int t = threadIdx.x; t < 30 * 96; t += 256) {
        int bin = t / 96, w = t - bin * 96;
        int rs, re;
        if      (bin == 0) { rs = 0; re = 96; }
        else if (bin < 4)  { int i = bin - 1;  rs = (i * 96) / 3;  re = ((i + 1) * 96 + 2) / 3; }
        else if (bin < 9)  { int i = bin - 4;  rs = (i * 96) / 5;  re = ((i + 1) * 96 + 4) / 5; }
        else if (bin < 16) { int i = bin - 9;  rs = (i * 96) / 7;  re = ((i + 1) * 96 + 6) / 7; }
        else               { int i = bin - 16; rs = (i * 96) / 14; re = ((i + 1) * 96 + 13) / 14; }
        float hi = tile[re - 1][w];
        float lo = rs ? tile[rs - 1][w] : 0.f;
        rb[bin][w] = hi - lo;
    }
    __syncthreads();

    for (int p = threadIdx.x; p < PP; p += 256) {
        int rs, re, cs, ce, rbb_i;
        if (p < 1) {
            rs = 0; re = 96; cs = 0; ce = 96; rbb_i = 0;
        } else if (p < 10) {
            int q = p - 1, i = q / 3, j = q - i * 3;
            rs = (i * 96) / 3;  re = ((i + 1) * 96 + 2) / 3;
            cs = (j * 96) / 3;  ce = ((j + 1) * 96 + 2) / 3;
            rbb_i = 1 + i;
        } else if (p < 35) {
            int q = p - 10, i = q / 5, j = q - i * 5;
            rs = (i * 96) / 5;  re = ((i + 1) * 96 + 4) / 5;
            cs = (j * 96) / 5;  ce = ((j + 1) * 96 + 4) / 5;
            rbb_i = 4 + i;
        } else if (p < 84) {
            int q = p - 35, i = q / 7, j = q - i * 7;
            rs = (i * 96) / 7;  re = ((i + 1) * 96 + 6) / 7;
            cs = (j * 96) / 7;  ce = ((j + 1) * 96 + 6) / 7;
            rbb_i = 9 + i;
        } else {
            int q = p - 84, i = q / 14, j = q - i * 14;
            rs = (i * 96) / 14; re = ((i + 1) * 96 + 13) / 14;
            cs = (j * 96) / 14; ce = ((j + 1) * 96 + 13) / 14;
            rbb_i = 16 + i;
        }
        float sum = 0.f;
        for (int w = cs; w < ce; w++) sum += rb[rbb_i][w];
        dst[(size_t)ch * PP + p] = sum / (float)((re - rs) * (ce - cs));
    }
}

// ---------------- K2: projk = wk @ P2 + bk, plus per-tile S partials ----------------
__global__ void __launch_bounds__(256) projk_kernel(const float* __restrict__ wk,
                                                    const float* __restrict__ bk) {
    __shared__ float pt[256][14];
    __shared__ float red[32][14];
    int b = blockIdx.y, p0 = blockIdx.x * 14;
    for (int i = threadIdx.x; i < 256 * 14; i += 256) {
        int c = i / 14, pp = i - c * 14;
        pt[c][pp] = g_P2[((size_t)(b * 256 + c)) * PP + p0 + pp];
    }
    __syncthreads();
    for (int oi = threadIdx.x; oi < 32 * 14; oi += 256) {
        int j = oi / 14, pp = oi - j * 14;
        float sum = 0.f;
        #pragma unroll 8
        for (int c = 0; c < 256; c++)
            sum += __ldg(wk + j * 256 + c) * pt[c][pp];
        float v = bk[j] + sum;
        g_pk[((size_t)(b * 32 + j)) * PP + p0 + pp] = v;
        red[j][pp] = v;
    }
    __syncthreads();
    if (threadIdx.x < 32) {
        float s = 0.f;
        #pragma unroll
        for (int pp = 0; pp < 14; pp++) s += red[threadIdx.x][pp];
        g_Sp[((size_t)b * 20 + blockIdx.x) * 32 + threadIdx.x] = s;
    }
}

// ---------------- K4: G[b,c,j] = sum_p P1[b,c,p]*projk[b,j,p] ----------------
__global__ void __launch_bounds__(128) gmat_kernel() {
    __shared__ float pk_s[32 * 281];
    int b = blockIdx.y, c = blockIdx.x * 16 + (threadIdx.x >> 3);
    int jg = (threadIdx.x & 7) * 4;
    for (int i = threadIdx.x; i < 32 * 280; i += 128)
        pk_s[(i / 280) * 281 + (i % 280)] = g_pk[(size_t)b * 32 * PP + i];
    __syncthreads();
    const float* p1 = g_P1 + ((size_t)(b * 256 + c)) * PP;
    float acc[4];
    #pragma unroll
    for (int k = 0; k < 4; k++) acc[k] = 0.f;
    #pragma unroll 4
    for (int p = 0; p < PP; p++) {
        float xv = __ldg(p1 + p);
        #pragma unroll
        for (int k = 0; k < 4; k++) acc[k] += xv * pk_s[(jg + k) * 281 + p];
    }
    #pragma unroll
    for (int k = 0; k < 4; k++)
        g_G[((size_t)(b * 256 + c)) * 32 + jg + k] = acc[k];
}

// ---------------- K5: aff = sigmoid(wq @ G + bq*S) ----------------
__global__ void __launch_bounds__(128) aff_kernel(const float* __restrict__ wq,
                                                  const float* __restrict__ bq) {
    __shared__ float Gs[256 * 33];
    __shared__ float Ss[32];
    int b = blockIdx.y;
    int o = blockIdx.x * 16 + (threadIdx.x >> 3);
    int cg = threadIdx.x & 7;
    if (threadIdx.x < 32) {
        float s = 0.f;
        #pragma unroll
        for (int t = 0; t < 20; t++)
            s += g_Sp[((size_t)b * 20 + t) * 32 + threadIdx.x];
        Ss[threadIdx.x] = s;
    }
    for (int i = threadIdx.x; i < 8192; i += 128)
        Gs[(i >> 5) * 33 + (i & 31)] = g_G[(size_t)b * 8192 + i];
    __syncthreads();
    float acc[32];
    #pragma unroll
    for (int j = 0; j < 32; j++) acc[j] = 0.f;
    for (int cc = 0; cc < 32; cc++) {
        int c = cg + cc * 8;
        float wv = __ldg(wq + o * 256 + c);
        #pragma unroll
        for (int j = 0; j < 32; j++) acc[j] += wv * Gs[c * 33 + j];
    }
    #pragma unroll
    for (int j = 0; j < 32; j++) {
        acc[j] += __shfl_xor_sync(0xffffffffu, acc[j], 1);
        acc[j] += __shfl_xor_sync(0xffffffffu, acc[j], 2);
        acc[j] += __shfl_xor_sync(0xffffffffu, acc[j], 4);
    }
    if (cg == 0) {
        float bqo = __ldg(bq + o);
        #pragma unroll
        for (int j = 0; j < 32; j++) {
            float z = acc[j] + bqo * Ss[j];
            g_aff[((size_t)(b * 256 + o)) * 32 + j] = 1.f / (1.f + expf(-z));
        }
    }
}

// ---------------- K6: conv3x3, dual-layout smem; occupancy cap 5 + packed slots -----
// 16 warps/SM at <=102 regs leaves ~13K regs free so chain-B kernels can co-reside
// (at 128 regs the RF was completely full -> no overlap).
// Slot packing: X0 vec16 slot = ok<<31 | (dstByte/16)<<13 | srcByte/16
//               X1 scalar slot = ok<<31 | (dstFloat)<<15 | srcFloat
#define X0_BUF_B 2880                  // 2*10*36*4
#define X1_BUF_B 3520                  // 2*10*44*4
#define W_BUF_B  6144                  // 2*32*12*8
__global__ void __launch_bounds__(128, 5) conv_kernel(const float* __restrict__ x1) {
    __shared__ __align__(16) float in0_s[3][2][10][36];   //  8640 B
    __shared__ __align__(16) float in1_s[3][2][10][44];   // 10560 B
    __shared__ __align__(16) ull   w_s[3][2][32 * 12];    // 18432 B (total 37632 B)
    int tile = blockIdx.x, b = blockIdx.y, chalf = blockIdx.z;
    int tX = (tile % 3) * 32, tY = (tile / 3) * 8;
    int jh = threadIdx.x >> 5;
    int lane = threadIdx.x & 31;
    int ty = lane >> 2, tx = lane & 3;
    int cbase = chalf * 128;
    float* yout = chalf ? g_yb : g_ya;
    const char* xb0 = (const char*)(x1 + (size_t)(b * 256 + cbase) * HW);
    const char* wsrc0 = (const char*)g_w2p + (size_t)cbase * 3072;

    // ---- packed X0 slots (vec16): 160 jobs ----
    unsigned x0p[2];
    #pragma unroll
    for (int t = 0; t < 2; t++) {
        int i = threadIdx.x + t * 128;           // < 160 used
        int r = i >> 3, c4 = (i & 7) * 4;
        int cc = r / 10, rr = r - cc * 10;
        int gy = tY - 1 + rr;
        unsigned ok = ((unsigned)gy < 96u) ? 1u : 0u;
        unsigned d16 = (unsigned)(((cc * 10 + rr) * 36 + c4)) >> 2;          // byte/16
        unsigned s16 = (unsigned)((cc * HW + (ok ? gy : 0) * 96 + tX + c4)) >> 2;
        x0p[t] = (ok << 31) | (d16 << 13) | s16;
    }
    // ---- packed X1 slots (scalar): 680 jobs ----
    unsigned x1p[6];
    #pragma unroll
    for (int t = 0; t < 6; t++) {
        int i = threadIdx.x + t * 128;           // < 680 used
        if (i < 680) {
            int r = i / 34, c = i - r * 34;
            int cc = r / 10, rr = r - cc * 10;
            int gy = tY - 1 + rr;
            int gx = tX + c - 1;
            unsigned ok = (((unsigned)gy < 96u) && ((unsigned)gx < 96u)) ? 1u : 0u;
            unsigned d4 = (unsigned)((cc * 10 + rr) * 44 + 4 + c);
            unsigned s4v = (unsigned)(cc * HW + (ok ? gy : 0) * 96 + (ok ? gx : 0));
            x1p[t] = (ok << 31) | (d4 << 15) | s4v;
        } else {
            x1p[t] = 40u << 15;                  // scratch pad float of row 0, sz 0
        }
    }
    unsigned in0_u = s2u(&in0_s[0][0][0][0]);
    unsigned in1_u = s2u(&in1_s[0][0][0][0]);
    unsigned w_u   = s2u(&w_s[0][0][0]);

    ull acc[8][4];
    #pragma unroll
    for (int j = 0; j < 8; j++)
        #pragma unroll
        for (int u = 0; u < 4; u++) acc[j][u] = 0ull;

    auto load_stage = [&](int s, int buf) {
        const char* sb = xb0 + (size_t)s * (2 * HW * 4);
        unsigned i0 = in0_u + buf * X0_BUF_B;
        unsigned i1 = in1_u + buf * X1_BUF_B;
        {
            unsigned p = x0p[0];
            cpa16z(i0 + ((p >> 13) & 0xFFu) * 16, sb + (p & 0x1FFFu) * 16,
                   ((int)p < 0) ? 16 : 0);
        }
        if (threadIdx.x < 32) {
            unsigned p = x0p[1];
            cpa16z(i0 + ((p >> 13) & 0xFFu) * 16, sb + (p & 0x1FFFu) * 16,
                   ((int)p < 0) ? 16 : 0);
        }
        #pragma unroll
        for (int t = 0; t < 6; t++) {
            unsigned p = x1p[t];
            cpa4z(i1 + ((p >> 15) & 0xFFFu) * 4, sb + (p & 0x7FFFu) * 4,
                  ((int)p < 0) ? 4 : 0);
        }
        const char* ws = wsrc0 + (size_t)s * 6144;
        unsigned wb = w_u + buf * W_BUF_B;
        cpa16(wb + threadIdx.x * 16, ws + threadIdx.x * 16);
        cpa16(wb + (threadIdx.x + 128) * 16, ws + (threadIdx.x + 128) * 16);
        cpa16(wb + (threadIdx.x + 256) * 16, ws + (threadIdx.x + 256) * 16);
    };

    load_stage(0, 0); CP_COMMIT();
    load_stage(1, 1); CP_COMMIT();

    int buf_c = 0, buf_n = 2;
    #pragma unroll 1
    for (int s = 0; s < 64; s++) {
        if (s < 63) { CP_WAIT1(); } else { CP_WAIT0(); }
        __syncthreads();
        if (s < 62) {
            load_stage(s + 2, buf_n);
            CP_COMMIT();
            if (++buf_n == 3) buf_n = 0;
        }

        #pragma unroll
        for (int cc = 0; cc < 2; cc++) {
            const ull* wp = &w_s[buf_c][cc][jh * 96];
            #pragma unroll
            for (int rr = 0; rr < 3; rr++) {
                const float* p0 = &in0_s[buf_c][cc][ty + rr][tx * 8];
                const float* p1 = &in1_s[buf_c][cc][ty + rr][4 + tx * 8];
                ulonglong2 q0 = *(const ulonglong2*)p0;
                ulonglong2 q1 = *(const ulonglong2*)(p0 + 4);
                ulonglong2 a  = *(const ulonglong2*)p1;
                ulonglong2 bb = *(const ulonglong2*)(p1 + 4);
                ull e = *(const ull*)(p1 + 8);
                #pragma unroll
                for (int jj = 0; jj < 8; jj++) {
                    int wo = jj * 12 + rr * 4;
                    ulonglong2 w01 = *(const ulonglong2*)&wp[wo];
                    ull w2 = wp[wo + 2];
                    fma2(acc[jj][0], w01.x, a.x);  fma2(acc[jj][1], w01.x, a.y);
                    fma2(acc[jj][2], w01.x, bb.x); fma2(acc[jj][3], w01.x, bb.y);
                    fma2(acc[jj][0], w01.y, q0.x); fma2(acc[jj][1], w01.y, q0.y);
                    fma2(acc[jj][2], w01.y, q1.x); fma2(acc[jj][3], w01.y, q1.y);
                    fma2(acc[jj][0], w2, a.y);     fma2(acc[jj][1], w2, bb.x);
                    fma2(acc[jj][2], w2, bb.y);    fma2(acc[jj][3], w2, e);
                }
            }
        }
        if (++buf_c == 3) buf_c = 0;
    }

    int gy = tY + ty, gx0 = tX + tx * 8;
    #pragma unroll
    for (int jj = 0; jj < 8; jj++) {
        float4 r0, r1;
        upk2f(acc[jj][0], r0.x, r0.y);
        upk2f(acc[jj][1], r0.z, r0.w);
        upk2f(acc[jj][2], r1.x, r1.y);
        upk2f(acc[jj][3], r1.z, r1.w);
        float* op = yout + ((size_t)(b * 32 + jh * 8 + jj) * 96 + gy) * 96 + gx0;
        *(float4*)op = r0;
        *(float4*)(op + 4) = r1;
    }
}

// ---------------- K7: out[b,o,p] = sum_j aff[b,o,j] * (ya+yb)[b,j,p] ----------------
__global__ void __launch_bounds__(128) mix_kernel(float* __restrict__ out) {
    __shared__ float2 af2[128 * 32];   // 32 KB
    int b = blockIdx.y, oh = blockIdx.z;
    int p0 = blockIdx.x * 256 + threadIdx.x * 2;
    for (int i = threadIdx.x; i < 4096; i += 128) {
        float a = g_aff[(size_t)b * 8192 + oh * 4096 + i];
        af2[i] = make_float2(a, a);
    }
    __syncthreads();

    ull y[32];
    #pragma unroll
    for (int j = 0; j < 32; j++) {
        size_t off = ((size_t)(b * 32 + j)) * HW + p0;
        float2 a = *(const float2*)(g_ya + off);
        float2 c = *(const float2*)(g_yb + off);
        y[j] = pk2f(a.x + c.x, a.y + c.y);
    }
    #pragma unroll 1
    for (int o = 0; o < 128; o++) {
        const ull* ao = (const ull*)&af2[o * 32];
        ull s0 = 0ull, s1 = 0ull;
        #pragma unroll
        for (int j = 0; j < 32; j += 2) {
            fma2(s0, ao[j], y[j]);
            fma2(s1, ao[j + 1], y[j + 1]);
        }
        ull sa = add2(s0, s1);
        float2 r;
        upk2f(sa, r.x, r.y);
        *(float2*)(out + ((size_t)(b * 256 + oh * 128 + o)) * HW + p0) = r;
    }
}

// ---------------- launch: fork conv onto a side stream (conv at code idx 3) ---------
// Graph shape:  w2prep ─┬─ conv ───────────────────────┬─ mix
//                       └─ pool,pool,projk,gmat,aff ───┘
extern "C" void kernel_launch(void* const* d_in, const int* in_sizes, int n_in,
                              void* d_out, int out_size) {
    const float* x_1 = (const float*)d_in[0];
    const float* x   = (const float*)d_in[1];
    const float* wq  = (const float*)d_in[2];
    const float* bq  = (const float*)d_in[3];
    const float* wk  = (const float*)d_in[4];
    const float* bk  = (const float*)d_in[5];
    const float* con = (const float*)d_in[6];
    float* out = (float*)d_out;

    cudaStream_t s2;
    cudaEvent_t eFork, eJoin;
    cudaStreamCreateWithFlags(&s2, cudaStreamNonBlocking);
    cudaEventCreateWithFlags(&eFork, cudaEventDisableTiming);
    cudaEventCreateWithFlags(&eJoin, cudaEventDisableTiming);

    w2prep_kernel<<<384, 256>>>(con);                     // idx 0 (capture stream)
    cudaEventRecord(eFork, 0);
    cudaStreamWaitEvent(s2, eFork, 0);

    pool_kernel  <<<2048, 256>>>(x_1, 0);                 // idx 1
    pool_kernel  <<<2048, 256>>>(x,   1);                 // idx 2
    conv_kernel  <<<dim3(36, 8, 2), 128, 0, s2>>>(x_1);   // idx 3 (branch) -> profiled
    projk_kernel <<<dim3(20, 8), 256>>>(wk, bk);          // idx 4
    gmat_kernel  <<<dim3(16, 8), 128>>>();                // idx 5
    aff_kernel   <<<dim3(16, 8), 128>>>(wq, bq);          // idx 6

    cudaEventRecord(eJoin, s2);
    cudaStreamWaitEvent(0, eJoin, 0);
    mix_kernel   <<<dim3(36, 8, 2), 128>>>(out);          // idx 7
}

// round 17
// speedup vs baseline: 1.1186x; 1.1186x over previous
#include <cuda_runtime.h>

#define B_  8
#define C_  256
#define C8  32
#define H_  96
#define W_  96
#define HW  9216
#define PP  280

typedef unsigned long long ull;

// ---------------- scratch (device globals; no allocation allowed) ----------------
__device__ float g_P1[B_*C_*PP];       // PSP(x_1)  [8,256,280]
__device__ float g_P2[B_*C_*PP];       // PSP(x)    [8,256,280]
__device__ float g_pk[B_*C8*PP];       // projk     [8,32,280]
__device__ float g_Sp[B_*20*C8];       // per-tile partial sums of projk
__device__ float g_G [B_*C_*C8];       // P1 . projk^T  [8,256,32]
__device__ float g_aff[B_*C_*C8];      // sigmoid(...)  [8,256,32]
__device__ float g_ya[B_*C8*HW];       // conv partial (c 0..127)
__device__ float g_yb[B_*C8*HW];       // conv partial (c 128..255)
// duplicated + padded conv weights: [c][j][rr][4] float2 (k=3 pad = 0)
__device__ __align__(16) float2 g_w2p[C_*C8*12];

// ---------------- f32x2 helpers ----------------
__device__ __forceinline__ ull pk2f(float lo, float hi) {
    ull r;
    asm("mov.b64 %0, {%1, %2};" : "=l"(r) : "f"(lo), "f"(hi));
    return r;
}
__device__ __forceinline__ void upk2f(ull v, float& lo, float& hi) {
    asm("mov.b64 {%0, %1}, %2;" : "=f"(lo), "=f"(hi) : "l"(v));
}
__device__ __forceinline__ void fma2(ull& acc, ull a, ull b) {
    asm("fma.rn.f32x2 %0, %1, %2, %0;" : "+l"(acc) : "l"(a), "l"(b));
}
__device__ __forceinline__ ull add2(ull a, ull b) {
    ull r;
    asm("add.rn.f32x2 %0, %1, %2;" : "=l"(r) : "l"(a), "l"(b));
    return r;
}

// ---------------- cp.async helpers ----------------
__device__ __forceinline__ unsigned s2u(const void* p) {
    return (unsigned)__cvta_generic_to_shared(p);
}
__device__ __forceinline__ void cpa4z(unsigned d, const void* s, int sz) {
    asm volatile("cp.async.ca.shared.global [%0], [%1], 4, %2;" :: "r"(d), "l"(s), "r"(sz));
}
__device__ __forceinline__ void cpa16(unsigned d, const void* s) {
    asm volatile("cp.async.cg.shared.global [%0], [%1], 16;" :: "r"(d), "l"(s));
}
__device__ __forceinline__ void cpa16z(unsigned d, const void* s, int sz) {
    asm volatile("cp.async.cg.shared.global [%0], [%1], 16, %2;" :: "r"(d), "l"(s), "r"(sz));
}
#define CP_COMMIT() asm volatile("cp.async.commit_group;" ::: "memory")
#define CP_WAIT1()  asm volatile("cp.async.wait_group 1;"  ::: "memory")
#define CP_WAIT0()  asm volatile("cp.async.wait_group 0;"  ::: "memory")

// ---------------- K0: duplicate conv weights, padded [c][j][rr][4] ----------------
__global__ void __launch_bounds__(256) w2prep_kernel(const float* __restrict__ con) {
    int idx = blockIdx.x * 256 + threadIdx.x;      // < 98304
    int c = idx / 384, rem = idx - c * 384;
    int j = rem / 12, r2 = rem - j * 12;
    int rr = r2 >> 2, k = r2 & 3;
    float w = (k < 3) ? con[j * 2304 + c * 9 + rr * 3 + k] : 0.f;
    g_w2p[idx] = make_float2(w, w);
}

// ---------------- K1: adaptive pyramid pooling — column prefix-sum version ----------
__global__ void __launch_bounds__(256) pool_kernel(const float* __restrict__ src,
                                                   int which) {
    __shared__ float tile[96][97];
    __shared__ float rb[30][96];
    int ch = blockIdx.x;                           // b*C + c
    float* dst = which ? g_P2 : g_P1;

    const float4* s4 = (const float4*)(src + (size_t)ch * HW);
    for (int i = threadIdx.x; i < HW / 4; i += 256) {
        float4 v = s4[i];
        int li = i * 4, r = li / 96, c0 = li - r * 96;
        tile[r][c0] = v.x; tile[r][c0+1] = v.y; tile[r][c0+2] = v.z; tile[r][c0+3] = v.w;
    }
    __syncthreads();

    // Phase B: in-place inclusive column prefix (threads 0..95, conflict-free)
    if (threadIdx.x < 96) {
        int w = threadIdx.x;
        float acc = 0.f;
        #pragma unroll 8
        for (int h = 0; h < 96; h++) { acc += tile[h][w]; tile[h][w] = acc; }
    }
    __syncthreads();

    // 30 1D row-bins from prefix differences; literal divisors only (no IDIV).
    for (int t = threadIdx.x; t < 30 * 96; t += 256) {
        int bin = t / 96, w = t - bin * 96;
        int rs, re;
        if      (bin == 0) { rs = 0; re = 96; }
        else if (bin < 4)  { int i = bin - 1;  rs = (i * 96) / 3;  re = ((i + 1) * 96 + 2) / 3; }
        else if (bin < 9)  { int i = bin - 4;  rs = (i * 96) / 5;  re = ((i + 1) * 96 + 4) / 5; }
        else if (bin < 16) { int i = bin - 9;  rs = (i * 96) / 7;  re = ((i + 1) * 96 + 6) / 7; }
        else               { int i = bin - 16; rs = (i * 96) / 14; re = ((i + 1) * 96 + 13) / 14; }
        float hi = tile[re - 1][w];
        float lo = rs ? tile[rs - 1][w] : 0.f;
        rb[bin][w] = hi - lo;
    }
    __syncthreads();

    for (int p = threadIdx.x; p < PP; p += 256) {
        int rs, re, cs, ce, rbb_i;
        if (p < 1) {
            rs = 0; re = 96; cs = 0; ce = 96; rbb_i = 0;
        } else if (p < 10) {
            int q = p - 1, i = q / 3, j = q - i * 3;
            rs = (i * 96) / 3;  re = ((i + 1) * 96 + 2) / 3;
            cs = (j * 96) / 3;  ce = ((j + 1) * 96 + 2) / 3;
            rbb_i = 1 + i;
        } else if (p < 35) {
            int q = p - 10, i = q / 5, j = q - i * 5;
            rs = (i * 96) / 5;  re = ((i + 1) * 96 + 4) / 5;
            cs = (j * 96) / 5;  ce = ((j + 1) * 96 + 4) / 5;
            rbb_i = 4 + i;
        } else if (p < 84) {
            int q = p - 35, i = q / 7, j = q - i * 7;
            rs = (i * 96) / 7;  re = ((i + 1) * 96 + 6) / 7;
            cs = (j * 96) / 7;  ce = ((j + 1) * 96 + 6) / 7;
            rbb_i = 9 + i;
        } else {
            int q = p - 84, i = q / 14, j = q - i * 14;
            rs = (i * 96) / 14; re = ((i + 1) * 96 + 13) / 14;
            cs = (j * 96) / 14; ce = ((j + 1) * 96 + 13) / 14;
            rbb_i = 16 + i;
        }
        float sum = 0.f;
        for (int w = cs; w < ce; w++) sum += rb[rbb_i][w];
        dst[(size_t)ch * PP + p] = sum / (float)((re - rs) * (ce - cs));
    }
}

// ---------------- K2: projk = wk @ P2 + bk, plus per-tile S partials ----------------
__global__ void __launch_bounds__(256) projk_kernel(const float* __restrict__ wk,
                                                    const float* __restrict__ bk) {
    __shared__ float pt[256][14];
    __shared__ float red[32][14];
    int b = blockIdx.y, p0 = blockIdx.x * 14;
    for (int i = threadIdx.x; i < 256 * 14; i += 256) {
        int c = i / 14, pp = i - c * 14;
        pt[c][pp] = g_P2[((size_t)(b * 256 + c)) * PP + p0 + pp];
    }
    __syncthreads();
    for (int oi = threadIdx.x; oi < 32 * 14; oi += 256) {
        int j = oi / 14, pp = oi - j * 14;
        float sum = 0.f;
        #pragma unroll 8
        for (int c = 0; c < 256; c++)
            sum += __ldg(wk + j * 256 + c) * pt[c][pp];
        float v = bk[j] + sum;
        g_pk[((size_t)(b * 32 + j)) * PP + p0 + pp] = v;
        red[j][pp] = v;
    }
    __syncthreads();
    if (threadIdx.x < 32) {
        float s = 0.f;
        #pragma unroll
        for (int pp = 0; pp < 14; pp++) s += red[threadIdx.x][pp];
        g_Sp[((size_t)b * 20 + blockIdx.x) * 32 + threadIdx.x] = s;
    }
}

// ---------------- K4: G[b,c,j] = sum_p P1[b,c,p]*projk[b,j,p] ----------------
__global__ void __launch_bounds__(128) gmat_kernel() {
    __shared__ float pk_s[32 * 281];
    int b = blockIdx.y, c = blockIdx.x * 16 + (threadIdx.x >> 3);
    int jg = (threadIdx.x & 7) * 4;
    for (int i = threadIdx.x; i < 32 * 280; i += 128)
        pk_s[(i / 280) * 281 + (i % 280)] = g_pk[(size_t)b * 32 * PP + i];
    __syncthreads();
    const float* p1 = g_P1 + ((size_t)(b * 256 + c)) * PP;
    float acc[4];
    #pragma unroll
    for (int k = 0; k < 4; k++) acc[k] = 0.f;
    #pragma unroll 4
    for (int p = 0; p < PP; p++) {
        float xv = __ldg(p1 + p);
        #pragma unroll
        for (int k = 0; k < 4; k++) acc[k] += xv * pk_s[(jg + k) * 281 + p];
    }
    #pragma unroll
    for (int k = 0; k < 4; k++)
        g_G[((size_t)(b * 256 + c)) * 32 + jg + k] = acc[k];
}

// ---------------- K5: aff = sigmoid(wq @ G + bq*S) ----------------
__global__ void __launch_bounds__(128) aff_kernel(const float* __restrict__ wq,
                                                  const float* __restrict__ bq) {
    __shared__ float Gs[256 * 33];
    __shared__ float Ss[32];
    int b = blockIdx.y;
    int o = blockIdx.x * 16 + (threadIdx.x >> 3);
    int cg = threadIdx.x & 7;
    if (threadIdx.x < 32) {
        float s = 0.f;
        #pragma unroll
        for (int t = 0; t < 20; t++)
            s += g_Sp[((size_t)b * 20 + t) * 32 + threadIdx.x];
        Ss[threadIdx.x] = s;
    }
    for (int i = threadIdx.x; i < 8192; i += 128)
        Gs[(i >> 5) * 33 + (i & 31)] = g_G[(size_t)b * 8192 + i];
    __syncthreads();
    float acc[32];
    #pragma unroll
    for (int j = 0; j < 32; j++) acc[j] = 0.f;
    for (int cc = 0; cc < 32; cc++) {
        int c = cg + cc * 8;
        float wv = __ldg(wq + o * 256 + c);
        #pragma unroll
        for (int j = 0; j < 32; j++) acc[j] += wv * Gs[c * 33 + j];
    }
    #pragma unroll
    for (int j = 0; j < 32; j++) {
        acc[j] += __shfl_xor_sync(0xffffffffu, acc[j], 1);
        acc[j] += __shfl_xor_sync(0xffffffffu, acc[j], 2);
        acc[j] += __shfl_xor_sync(0xffffffffu, acc[j], 4);
    }
    if (cg == 0) {
        float bqo = __ldg(bq + o);
        #pragma unroll
        for (int j = 0; j < 32; j++) {
            float z = acc[j] + bqo * Ss[j];
            g_aff[((size_t)(b * 256 + o)) * 32 + j] = 1.f / (1.f + expf(-z));
        }
    }
}

// ---------------- K6: conv3x3, dual-layout smem — R10/R15 SASS (128 regs) -----------
// Smem padded to ~60 KB/block so only 3 blocks/SM fit -> 49K regs used, 16K free for
// chain-B co-residency (at 4 blocks the RF was completely full -> no overlap in R15).
#define X0_BUF_B 2880                  // 2*10*36*4
#define X1_BUF_B 3520                  // 2*10*44*4
#define W_BUF_B  6144                  // 2*32*12*8
__global__ void __launch_bounds__(128, 3) conv_kernel(const float* __restrict__ x1) {
    __shared__ __align__(16) float in0_s[3][2][10][36];   //  8640 B
    __shared__ __align__(16) float in1_s[3][2][10][44];   // 10560 B
    __shared__ __align__(16) ull   w_s[3][2][32 * 12];    // 18432 B
    __shared__ __align__(16) ull   pad_s[2800];           // 22400 B pad -> ~60 KB total
    int tile = blockIdx.x, b = blockIdx.y, chalf = blockIdx.z;
    if ((int)blockIdx.x < -1) pad_s[threadIdx.x] = 0;     // keep pad alive (never true)
    int tX = (tile % 3) * 32, tY = (tile / 3) * 8;
    int jh = threadIdx.x >> 5;
    int lane = threadIdx.x & 31;
    int ty = lane >> 2, tx = lane & 3;
    int cbase = chalf * 128;
    float* yout = chalf ? g_yb : g_ya;
    const char* xb0 = (const char*)(x1 + (size_t)(b * 256 + cbase) * HW);
    const char* wsrc0 = (const char*)g_w2p + (size_t)cbase * 3072;

    unsigned x0d[2], x0s[2]; int x0z[2];
    #pragma unroll
    for (int t = 0; t < 2; t++) {
        int i = threadIdx.x + t * 128;           // < 160 used
        int r = i >> 3, c4 = (i & 7) * 4;
        int cc = r / 10, rr = r - cc * 10;
        int gy = tY - 1 + rr;
        int ok = (unsigned)gy < 96u;
        x0d[t] = (unsigned)(((cc * 10 + rr) * 36 + c4) * 4);
        x0s[t] = (unsigned)((cc * HW + (ok ? gy : 0) * 96 + tX + c4) * 4);
        x0z[t] = ok ? 16 : 0;
    }
    unsigned x1d[6], x1s[6]; int x1z[6];
    #pragma unroll
    for (int t = 0; t < 6; t++) {
        int i = threadIdx.x + t * 128;           // < 680 used
        if (i < 680) {
            int r = i / 34, c = i - r * 34;
            int cc = r / 10, rr = r - cc * 10;
            int gy = tY - 1 + rr;
            int gx = tX + c - 1;
            int ok = ((unsigned)gy < 96u) && ((unsigned)gx < 96u);
            x1d[t] = (unsigned)(((cc * 10 + rr) * 44 + 4 + c) * 4);
            x1s[t] = (unsigned)((cc * HW + (ok ? gy : 0) * 96 + (ok ? gx : 0)) * 4);
            x1z[t] = ok ? 4 : 0;
        } else {
            x1d[t] = 160;
            x1s[t] = 0;
            x1z[t] = 0;
        }
    }
    unsigned in0_u = s2u(&in0_s[0][0][0][0]);
    unsigned in1_u = s2u(&in1_s[0][0][0][0]);
    unsigned w_u   = s2u(&w_s[0][0][0]);

    ull acc[8][4];
    #pragma unroll
    for (int j = 0; j < 8; j++)
        #pragma unroll
        for (int u = 0; u < 4; u++) acc[j][u] = 0ull;

    auto load_stage = [&](int s, int buf) {
        const char* sb = xb0 + (size_t)s * (2 * HW * 4);
        unsigned i0 = in0_u + buf * X0_BUF_B;
        unsigned i1 = in1_u + buf * X1_BUF_B;
        cpa16z(i0 + x0d[0], sb + x0s[0], x0z[0]);
        if (threadIdx.x < 32)
            cpa16z(i0 + x0d[1], sb + x0s[1], x0z[1]);
        #pragma unroll
        for (int t = 0; t < 6; t++)
            cpa4z(i1 + x1d[t], sb + x1s[t], x1z[t]);
        const char* ws = wsrc0 + (size_t)s * 6144;
        unsigned wb = w_u + buf * W_BUF_B;
        cpa16(wb + threadIdx.x * 16, ws + threadIdx.x * 16);
        cpa16(wb + (threadIdx.x + 128) * 16, ws + (threadIdx.x + 128) * 16);
        cpa16(wb + (threadIdx.x + 256) * 16, ws + (threadIdx.x + 256) * 16);
    };

    load_stage(0, 0); CP_COMMIT();
    load_stage(1, 1); CP_COMMIT();

    int buf_c = 0, buf_n = 2;
    #pragma unroll 1
    for (int s = 0; s < 64; s++) {
        if (s < 63) { CP_WAIT1(); } else { CP_WAIT0(); }
        __syncthreads();
        if (s < 62) {
            load_stage(s + 2, buf_n);
            CP_COMMIT();
            if (++buf_n == 3) buf_n = 0;
        }

        #pragma unroll
        for (int cc = 0; cc < 2; cc++) {
            const ull* wp = &w_s[buf_c][cc][jh * 96];
            #pragma unroll
            for (int rr = 0; rr < 3; rr++) {
                const float* p0 = &in0_s[buf_c][cc][ty + rr][tx * 8];
                const float* p1 = &in1_s[buf_c][cc][ty + rr][4 + tx * 8];
                ulonglong2 q0 = *(const ulonglong2*)p0;
                ulonglong2 q1 = *(const ulonglong2*)(p0 + 4);
                ulonglong2 a  = *(const ulonglong2*)p1;
                ulonglong2 bb = *(const ulonglong2*)(p1 + 4);
                ull e = *(const ull*)(p1 + 8);
                #pragma unroll
                for (int jj = 0; jj < 8; jj++) {
                    int wo = jj * 12 + rr * 4;
                    ulonglong2 w01 = *(const ulonglong2*)&wp[wo];
                    ull w2 = wp[wo + 2];
                    fma2(acc[jj][0], w01.x, a.x);  fma2(acc[jj][1], w01.x, a.y);
                    fma2(acc[jj][2], w01.x, bb.x); fma2(acc[jj][3], w01.x, bb.y);
                    fma2(acc[jj][0], w01.y, q0.x); fma2(acc[jj][1], w01.y, q0.y);
                    fma2(acc[jj][2], w01.y, q1.x); fma2(acc[jj][3], w01.y, q1.y);
                    fma2(acc[jj][0], w2, a.y);     fma2(acc[jj][1], w2, bb.x);
                    fma2(acc[jj][2], w2, bb.y);    fma2(acc[jj][3], w2, e);
                }
            }
        }
        if (++buf_c == 3) buf_c = 0;
    }

    int gy = tY + ty, gx0 = tX + tx * 8;
    #pragma unroll
    for (int jj = 0; jj < 8; jj++) {
        float4 r0, r1;
        upk2f(acc[jj][0], r0.x, r0.y);
        upk2f(acc[jj][1], r0.z, r0.w);
        upk2f(acc[jj][2], r1.x, r1.y);
        upk2f(acc[jj][3], r1.z, r1.w);
        float* op = yout + ((size_t)(b * 32 + jh * 8 + jj) * 96 + gy) * 96 + gx0;
        *(float4*)op = r0;
        *(float4*)(op + 4) = r1;
    }
}

// ---------------- K7: out[b,o,p] = sum_j aff[b,o,j] * (ya+yb)[b,j,p] ----------------
__global__ void __launch_bounds__(128) mix_kernel(float* __restrict__ out) {
    __shared__ float2 af2[128 * 32];   // 32 KB
    int b = blockIdx.y, oh = blockIdx.z;
    int p0 = blockIdx.x * 256 + threadIdx.x * 2;
    for (int i = threadIdx.x; i < 4096; i += 128) {
        float a = g_aff[(size_t)b * 8192 + oh * 4096 + i];
        af2[i] = make_float2(a, a);
    }
    __syncthreads();

    ull y[32];
    #pragma unroll
    for (int j = 0; j < 32; j++) {
        size_t off = ((size_t)(b * 32 + j)) * HW + p0;
        float2 a = *(const float2*)(g_ya + off);
        float2 c = *(const float2*)(g_yb + off);
        y[j] = pk2f(a.x + c.x, a.y + c.y);
    }
    #pragma unroll 1
    for (int o = 0; o < 128; o++) {
        const ull* ao = (const ull*)&af2[o * 32];
        ull s0 = 0ull, s1 = 0ull;
        #pragma unroll
        for (int j = 0; j < 32; j += 2) {
            fma2(s0, ao[j], y[j]);
            fma2(s1, ao[j + 1], y[j + 1]);
        }
        ull sa = add2(s0, s1);
        float2 r;
        upk2f(sa, r.x, r.y);
        *(float2*)(out + ((size_t)(b * 256 + oh * 128 + o)) * HW + p0) = r;
    }
}

// ---------------- launch: fork conv onto a side stream (conv at code idx 3) ---------
// Graph shape:  w2prep ─┬─ conv ───────────────────────┬─ mix
//                       └─ pool,pool,projk,gmat,aff ───┘
extern "C" void kernel_launch(void* const* d_in, const int* in_sizes, int n_in,
                              void* d_out, int out_size) {
    const float* x_1 = (const float*)d_in[0];
    const float* x   = (const float*)d_in[1];
    const float* wq  = (const float*)d_in[2];
    const float* bq  = (const float*)d_in[3];
    const float* wk  = (const float*)d_in[4];
    const float* bk  = (const float*)d_in[5];
    const float* con = (const float*)d_in[6];
    float* out = (float*)d_out;

    cudaStream_t s2;
    cudaEvent_t eFork, eJoin;
    cudaStreamCreateWithFlags(&s2, cudaStreamNonBlocking);
    cudaEventCreateWithFlags(&eFork, cudaEventDisableTiming);
    cudaEventCreateWithFlags(&eJoin, cudaEventDisableTiming);

    w2prep_kernel<<<384, 256>>>(con);                     // idx 0 (capture stream)
    cudaEventRecord(eFork, 0);
    cudaStreamWaitEvent(s2, eFork, 0);

    pool_kernel  <<<2048, 256>>>(x_1, 0);                 // idx 1
    pool_kernel  <<<2048, 256>>>(x,   1);                 // idx 2
    conv_kernel  <<<dim3(36, 8, 2), 128, 0, s2>>>(x_1);   // idx 3 (branch) -> profiled
    projk_kernel <<<dim3(20, 8), 256>>>(wk, bk);          // idx 4
    gmat_kernel  <<<dim3(16, 8), 128>>>();                // idx 5
    aff_kernel   <<<dim3(16, 8), 128>>>(wq, bq);          // idx 6

    cudaEventRecord(eJoin, s2);
    cudaStreamWaitEvent(0, eJoin, 0);
    mix_kernel   <<<dim3(36, 8, 2), 128>>>(out);          // idx 7
}